// round 13
// baseline (speedup 1.0000x reference)
#include <cuda_runtime.h>
#include <cuda_fp16.h>
#include <cstdint>
#include <cstddef>

#define T_STEPS 512
#define DH      2048
#define DI      64
#define DO      64
#define BATCH   128
#define NB      64
#define RSTR    136              // padded u32 row stride

// ---- device scratch ----
__device__ float    g_base[DH * BATCH];
__device__ float    g_part[4 * DH * BATCH];
__device__ unsigned g_win_h[64 * 1024];    // HC=32 chunks: [c][kt4][mt2][lane] uint4
__device__ unsigned g_wout_h[64 * 1024];   // [c][kt2][mt4][lane] uint4, K-permuted
__device__ unsigned g_wfrag[4 * 32 * 32 * 4 * 32 * 4];
__device__ unsigned g_spk[1024 * 128];

__device__ __forceinline__ float sigm_exact(float x) {
    return __fdividef(1.0f, 1.0f + __expf(-x));
}
__device__ __forceinline__ float sigm(float x) {
    float t;
    asm("tanh.approx.f32 %0, %1;" : "=f"(t) : "f"(0.5f * x));
    return fmaf(0.5f, t, 0.5f);
}
__device__ __forceinline__ unsigned packh2(float a, float b) {
    __half2 h = __floats2half2_rn(a, b);
    return *(unsigned*)&h;
}
__device__ __forceinline__ void mma_f16(float* c,
                                        uint4 a, unsigned b0, unsigned b1) {
    asm volatile("mma.sync.aligned.m16n8k16.row.col.f32.f16.f16.f32 "
                 "{%0,%1,%2,%3}, {%4,%5,%6,%7}, {%8,%9}, {%0,%1,%2,%3};"
                 : "+f"(c[0]), "+f"(c[1]), "+f"(c[2]), "+f"(c[3])
                 : "r"(a.x), "r"(a.y), "r"(a.z), "r"(a.w), "r"(b0), "r"(b1));
}
__device__ __forceinline__ uint32_t smem_u32(const void* p) {
    uint32_t a;
    asm("{ .reg .u64 t; cvta.to.shared.u64 t, %1; cvt.u32.u64 %0, t; }" : "=r"(a) : "l"(p));
    return a;
}
__device__ __forceinline__ void mbar_init(uint32_t a, uint32_t cnt) {
    asm volatile("mbarrier.init.shared.b64 [%0], %1;" :: "r"(a), "r"(cnt) : "memory");
}
__device__ __forceinline__ void mbar_expect(uint32_t a, uint32_t bytes) {
    asm volatile("mbarrier.arrive.expect_tx.shared.b64 _, [%0], %1;" :: "r"(a), "r"(bytes) : "memory");
}
__device__ __forceinline__ void mbar_wait(uint32_t a, uint32_t par) {
    asm volatile(
        "{\n\t.reg .pred P1;\n\t"
        "W_%=:\n\t"
        "mbarrier.try_wait.parity.acquire.cta.shared::cta.b64 P1, [%0], %1, 0x989680;\n\t"
        "@P1 bra.uni D_%=;\n\t"
        "bra.uni W_%=;\n\t"
        "D_%=:\n\t}"
        :: "r"(a), "r"(par) : "memory");
}
__device__ __forceinline__ void bulk_g2s(uint32_t dst, const void* src, uint32_t bytes, uint32_t mbar) {
    asm volatile("cp.async.bulk.shared::cluster.global.mbarrier::complete_tx::bytes [%0], [%1], %2, [%3];"
                 :: "r"(dst), "l"(src), "r"(bytes), "r"(mbar) : "memory");
}
__device__ __forceinline__ void bulk_s2g(void* dst, uint32_t src, uint32_t bytes) {
    asm volatile("cp.async.bulk.global.shared::cta.bulk_group [%0], [%1], %2;"
                 :: "l"(dst), "r"(src), "r"(bytes) : "memory");
}
__device__ __forceinline__ void bulk_commit() {
    asm volatile("cp.async.bulk.commit_group;" ::: "memory");
}
template <int N> __device__ __forceinline__ void bulk_wait() {
    asm volatile("cp.async.bulk.wait_group %0;" :: "n"(N) : "memory");
}
__device__ __forceinline__ void fence_async() {
    asm volatile("fence.proxy.async;" ::: "memory");
}

// ---------- kernel 1: packing ----------
__global__ void pack_all_kernel(const float* __restrict__ win,
                                const float* __restrict__ wout,
                                const float* __restrict__ r0,
                                const float* __restrict__ w_) {
    int bx = blockIdx.x;
    int tid = threadIdx.x;
    if (bx < 128) {
        int tg = (bx & 63) * 256 + tid;       // 0..16383
        int lane = tg & 31;
        uint4 oh;
        if (bx < 64) {
            // win (HC=32): tg = ((c*4+kt)*2+mt)*32+lane
            int mt = (tg >> 5) & 1;
            int kt = (tg >> 6) & 3;
            int c  = tg >> 8;
            int r  = c * 32 + mt * 16 + (lane >> 2);
            int k0 = kt * 16 + 2 * (lane & 3);
            oh.x = packh2(win[r * DI + k0],           win[r * DI + k0 + 1]);
            oh.y = packh2(win[(r + 8) * DI + k0],     win[(r + 8) * DI + k0 + 1]);
            oh.z = packh2(win[r * DI + k0 + 8],       win[r * DI + k0 + 9]);
            oh.w = packh2(win[(r + 8) * DI + k0 + 8], win[(r + 8) * DI + k0 + 9]);
            *(uint4*)(g_win_h + (size_t)tg * 4) = oh;
        } else {
            // wout (HC=32, K-permuted pairs (h,h+8)): tg = ((c*2+kt)*4+mt)*32+lane
            int mt = (tg >> 5) & 3;
            int kt = (tg >> 7) & 1;
            int c  = tg >> 8;
            int r  = mt * 16 + (lane >> 2);
            int h0 = c * 32 + kt * 16 + (lane & 3);
            int h2 = h0 + 4;
            oh.x = packh2(wout[r * DH + h0],       wout[r * DH + h0 + 8]);
            oh.y = packh2(wout[(r + 8) * DH + h0], wout[(r + 8) * DH + h0 + 8]);
            oh.z = packh2(wout[r * DH + h2],       wout[r * DH + h2 + 8]);
            oh.w = packh2(wout[(r + 8) * DH + h2], wout[(r + 8) * DH + h2 + 8]);
            *(uint4*)(g_wout_h + (size_t)tg * 4) = oh;
        }
    } else if (bx < 384) {
        int i = (bx - 128) * 256 + tid;
        int bp = i & 63;
        int kp = i >> 6;
        float2 ra = *(const float2*)(r0 + (size_t)(2 * kp) * BATCH + 2 * bp);
        float2 rb = *(const float2*)(r0 + (size_t)(2 * kp + 1) * BATCH + 2 * bp);
        uint2 o;
        o.x = packh2(sigm_exact(ra.x), sigm_exact(rb.x));
        o.y = packh2(sigm_exact(ra.y), sigm_exact(rb.y));
        *(uint2*)(g_spk + (size_t)kp * BATCH + 2 * bp) = o;
    } else {
        int tg = (bx - 384) * 256 + tid;
        int lane = tg & 31;
        int mt = (tg >> 5) & 3;
        int kt = (tg >> 7) & 31;
        int hc = (tg >> 12) & 31;
        int kq = tg >> 17;
        int r  = hc * 64 + mt * 16 + (lane >> 2);
        int k0 = kq * 512 + kt * 16 + 2 * (lane & 3);
        uint4 oh;
        oh.x = packh2(fabsf(w_[(size_t)r * DH + k0]),       fabsf(w_[(size_t)r * DH + k0 + 1]));
        oh.y = packh2(fabsf(w_[(size_t)(r + 8) * DH + k0]), fabsf(w_[(size_t)(r + 8) * DH + k0 + 1]));
        oh.z = packh2(fabsf(w_[(size_t)r * DH + k0 + 8]),   fabsf(w_[(size_t)r * DH + k0 + 9]));
        oh.w = packh2(fabsf(w_[(size_t)(r + 8) * DH + k0 + 8]), fabsf(w_[(size_t)(r + 8) * DH + k0 + 9]));
        *(uint4*)(g_wfrag + (size_t)tg * 4) = oh;
    }
}

// ---------- kernel 2: base GEMM partials ----------
__global__ void __launch_bounds__(256)
base_gemm_kernel() {
    int bx = blockIdx.x;
    int kq = bx >> 6;
    int hc = (bx >> 1) & 31;
    int nh = bx & 1;
    int tid  = threadIdx.x;
    int lane = tid & 31;
    int w    = tid >> 5;
    int qq   = lane & 3;
    int rr   = lane >> 2;
    int n    = nh * NB + w * 8 + rr;

    float C[4][4];
#pragma unroll
    for (int a = 0; a < 4; ++a)
#pragma unroll
        for (int q = 0; q < 4; ++q) C[a][q] = 0.0f;

    const uint4* Af = ((const uint4*)g_wfrag) + ((size_t)(kq * 32 + hc) * 32) * 128;
#pragma unroll 4
    for (int kt = 0; kt < 32; ++kt) {
        int kp = kq * 256 + kt * 8;
        unsigned b0 = g_spk[(size_t)(kp + qq) * BATCH + n];
        unsigned b1 = g_spk[(size_t)(kp + 4 + qq) * BATCH + n];
#pragma unroll
        for (int mt = 0; mt < 4; ++mt)
            mma_f16(C[mt], Af[(kt * 4 + mt) * 32 + lane], b0, b1);
    }
    float* dst = g_part + (size_t)kq * DH * BATCH;
    int n0 = nh * NB + w * 8 + 2 * qq;
#pragma unroll
    for (int mt = 0; mt < 4; ++mt)
#pragma unroll
        for (int hh = 0; hh < 2; ++hh) {
            int h = hc * 64 + mt * 16 + hh * 8 + rr;
            *(float2*)(dst + (size_t)h * BATCH + n0) =
                make_float2(C[mt][hh * 2], C[mt][hh * 2 + 1]);
        }
}

// ---------- kernel 3: base reduce ----------
__global__ void base_reduce_kernel(const float* __restrict__ r0,
                                   const float* __restrict__ taus) {
    int i4 = (blockIdx.x * blockDim.x + threadIdx.x) * 4;
    int h  = i4 >> 7;
    float alpha = 1.0f / taus[h];
    float om = 1.0f - alpha;
    float4 rv = *(const float4*)(r0 + i4);
    float4 p0 = *(const float4*)(g_part + i4);
    float4 p1 = *(const float4*)(g_part + DH * BATCH + i4);
    float4 p2 = *(const float4*)(g_part + 2 * DH * BATCH + i4);
    float4 p3 = *(const float4*)(g_part + 3 * DH * BATCH + i4);
    float4 o;
    o.x = om * rv.x + alpha * (p0.x + p1.x + p2.x + p3.x);
    o.y = om * rv.y + alpha * (p0.y + p1.y + p2.y + p3.y);
    o.z = om * rv.z + alpha * (p0.z + p1.z + p2.z + p3.z);
    o.w = om * rv.w + alpha * (p0.w + p1.w + p2.w + p3.w);
    *(float4*)(g_base + i4) = o;
}

// ---------- kernel 4: main — 1 t, full batch, bulk-async I/O ----------
// u32 offsets (16B aligned):
#define oMB  0
#define oW1  4
#define oW2  2052
#define oU   4100
#define oS   8452
#define oNZ0 10628
#define oNZ1 14980
#define oBS0 19332
#define oBS1 23684
#define oXS0 28036
#define oXS1 32388
#define SMEM_U32 36740

__global__ void __launch_bounds__(512, 1)
main_kernel(const float* __restrict__ u,
            const float* __restrict__ noise,
            const float* __restrict__ bias,
            float* __restrict__ out) {
    extern __shared__ unsigned smu[];
    uint32_t sb = smem_u32(smu);

    int tid  = threadIdx.x;
    int lane = tid & 31;
    int w    = tid >> 5;          // 0..15, n-slice w*8
    int qq   = lane & 3;
    int rr   = lane >> 2;
    int t    = blockIdx.x;

    int n0 = w * 8 + 2 * qq;      // col pair base
    int n  = w * 8 + rr;          // B-frag col

    float* xsout = out + (size_t)T_STEPS * DO * BATCH;

    if (tid == 0) { mbar_init(sb + oMB * 4, 16); mbar_init(sb + oMB * 4 + 8, 16); }
    __syncthreads();

    // issue chunk 0,1 loads (each warp lane0: rows 2w,2w+1)
    if (lane == 0) {
#pragma unroll
        for (int s = 0; s < 2; ++s) {
            uint32_t mb = sb + oMB * 4 + s * 8;
            mbar_expect(mb, 2048);
#pragma unroll
            for (int j = 0; j < 2; ++j) {
                int r  = 2 * w + j;
                int hg = s * 32 + r;
                bulk_g2s(sb + ((s ? oNZ1 : oNZ0) + r * RSTR) * 4,
                         noise + ((size_t)t * DH + hg) * BATCH, 512, mb);
                bulk_g2s(sb + ((s ? oBS1 : oBS0) + r * RSTR) * 4,
                         g_base + (size_t)hg * BATCH, 512, mb);
            }
        }
    }

    // stage u[t]: 32 dp-rows x 128 cols half2, stride RSTR
    {
        const float* ut = u + (size_t)t * DI * BATCH;
#pragma unroll
        for (int i = 0; i < 4; ++i) {
            int idx = tid + i * 512;      // 0..2047
            int dp  = idx >> 6;
            int b2  = (idx & 63) * 2;
            float2 ra = *(const float2*)(ut + (2 * dp) * BATCH + b2);
            float2 rb = *(const float2*)(ut + (2 * dp + 1) * BATCH + b2);
            *(uint2*)(smu + oU + dp * RSTR + b2) =
                make_uint2(packh2(ra.x, rb.x), packh2(ra.y, rb.y));
        }
    }
    // stage W1[0,1], W2[0,1]
    ((uint4*)(smu + oW1))[tid] = ((const uint4*)g_win_h)[tid];
    ((uint4*)(smu + oW2))[tid] = ((const uint4*)g_wout_h)[tid];

    float C2[4][4];
#pragma unroll
    for (int a = 0; a < 4; ++a)
#pragma unroll
        for (int q = 0; q < 4; ++q) C2[a][q] = 0.0f;

    __syncthreads();

    for (int c = 0; c < 64; ++c) {
        int buf = c & 1;
        uint32_t mb = sb + oMB * 4 + buf * 8;
        mbar_wait(mb, (c >> 1) & 1);

        // ---- GEMM1: C1 = win_chunk(32xDI) @ u ----
        const uint4* A1 = (const uint4*)(smu + oW1 + buf * 1024);
        float C1[2][4];
#pragma unroll
        for (int a = 0; a < 2; ++a)
#pragma unroll
            for (int q = 0; q < 4; ++q) C1[a][q] = 0.0f;
#pragma unroll
        for (int kt = 0; kt < 4; ++kt) {
            unsigned b0 = smu[oU + (kt * 8 + qq) * RSTR + n];
            unsigned b1 = smu[oU + (kt * 8 + 4 + qq) * RSTR + n];
#pragma unroll
            for (int mt = 0; mt < 2; ++mt)
                mma_f16(C1[mt], A1[(kt * 2 + mt) * 32 + lane], b0, b1);
        }

        // ---- epilogue: xs -> XS smem; sigm -> S (pair-permuted) ----
        const float* NZf = (const float*)(smu + (buf ? oNZ1 : oNZ0));
        const float* BSf = (const float*)(smu + (buf ? oBS1 : oBS0));
        float* XSf = (float*)(smu + (buf ? oXS1 : oXS0));
#pragma unroll
        for (int mt = 0; mt < 2; ++mt) {
            int ra = mt * 16 + rr;
            float2 nza = *(const float2*)(NZf + ra * RSTR + n0);
            float2 bsa = *(const float2*)(BSf + ra * RSTR + n0);
            float2 nzb = *(const float2*)(NZf + (ra + 8) * RSTR + n0);
            float2 bsb = *(const float2*)(BSf + (ra + 8) * RSTR + n0);
            float xa0 = C1[mt][0] + nza.x + bsa.x;
            float xa1 = C1[mt][1] + nza.y + bsa.y;
            float xb0 = C1[mt][2] + nzb.x + bsb.x;
            float xb1 = C1[mt][3] + nzb.y + bsb.y;
            *(float2*)(XSf + ra * RSTR + n0)       = make_float2(xa0, xa1);
            *(float2*)(XSf + (ra + 8) * RSTR + n0) = make_float2(xb0, xb1);
            *(uint2*)(smu + oS + (mt * 8 + rr) * RSTR + n0) =
                make_uint2(packh2(sigm(xa0), sigm(xb0)),
                           packh2(sigm(xa1), sigm(xb1)));
        }
        __syncthreads();   // sync1: XS/S done; NZ/BS/W1 free

        // ---- issue XS s2g (rows 2w,2w+1) ----
        if (lane == 0) {
            fence_async();
#pragma unroll
            for (int j = 0; j < 2; ++j) {
                int r = 2 * w + j;
                bulk_s2g(xsout + ((size_t)t * DH + c * 32 + r) * BATCH,
                         sb + ((buf ? oXS1 : oXS0) + r * RSTR) * 4, 512);
            }
            bulk_commit();
        }
        // ---- stage W1[c+2]; issue loads c+2 ----
        if (c + 2 < 64) {
            if (tid < 256)
                ((uint4*)(smu + oW1 + buf * 1024))[tid] =
                    ((const uint4*)g_win_h)[(c + 2) * 256 + tid];
            if (lane == 0) {
                mbar_expect(mb, 2048);
#pragma unroll
                for (int j = 0; j < 2; ++j) {
                    int r  = 2 * w + j;
                    int hg = (c + 2) * 32 + r;
                    bulk_g2s(sb + ((buf ? oNZ1 : oNZ0) + r * RSTR) * 4,
                             noise + ((size_t)t * DH + hg) * BATCH, 512, mb);
                    bulk_g2s(sb + ((buf ? oBS1 : oBS0) + r * RSTR) * 4,
                             g_base + (size_t)hg * BATCH, 512, mb);
                }
            }
        }

        // ---- GEMM2: C2 += wout_chunk @ S (permuted K) ----
        const uint4* A2 = (const uint4*)(smu + oW2 + buf * 1024);
#pragma unroll
        for (int kt = 0; kt < 2; ++kt) {
            unsigned s0 = smu[oS + (kt * 8 + qq) * RSTR + n];
            unsigned s1 = smu[oS + (kt * 8 + 4 + qq) * RSTR + n];
#pragma unroll
            for (int mt = 0; mt < 4; ++mt)
                mma_f16(C2[mt], A2[(kt * 4 + mt) * 32 + lane], s0, s1);
        }

        if (lane == 0) bulk_wait<1>();
        __syncthreads();   // sync2: S/W2 free; prior XS store drained

        if (c + 2 < 64 && tid < 256)
            ((uint4*)(smu + oW2 + buf * 1024))[tid] =
                ((const uint4*)g_wout_h)[(c + 2) * 256 + tid];
    }

    if (lane == 0) bulk_wait<0>();

    // ---- outputs[t] ----
#pragma unroll
    for (int mt = 0; mt < 4; ++mt) {
        int o0 = mt * 16 + rr;
        float bv0 = __ldg(bias + o0);
        float bv8 = __ldg(bias + o0 + 8);
        *(float2*)(out + ((size_t)t * DO + o0) * BATCH + n0) =
            make_float2(C2[mt][0] + bv0, C2[mt][1] + bv0);
        *(float2*)(out + ((size_t)t * DO + o0 + 8) * BATCH + n0) =
            make_float2(C2[mt][2] + bv8, C2[mt][3] + bv8);
    }
}

extern "C" void kernel_launch(void* const* d_in, const int* in_sizes, int n_in,
                              void* d_out, int out_size) {
    const float* u     = (const float*)d_in[0];
    const float* r0    = (const float*)d_in[1];
    const float* noise = (const float*)d_in[2];
    const float* win   = (const float*)d_in[3];
    const float* w_    = (const float*)d_in[4];
    // d_in[5] = m_diag: unused — |_w * (+-1)| == |_w|
    const float* wout  = (const float*)d_in[6];
    const float* bias  = (const float*)d_in[7];
    const float* taus  = (const float*)d_in[8];
    float* out = (float*)d_out;

    const int main_smem = SMEM_U32 * 4;   // 146960 B
    cudaFuncSetAttribute(main_kernel, cudaFuncAttributeMaxDynamicSharedMemorySize, main_smem);

    pack_all_kernel<<<2432, 256>>>(win, wout, r0, w_);
    base_gemm_kernel<<<256, 256>>>();
    base_reduce_kernel<<<256, 256>>>(r0, taus);
    main_kernel<<<T_STEPS, 512, main_smem>>>(u, noise, bias, out);
}

// round 15
// speedup vs baseline: 1.7363x; 1.7363x over previous
#include <cuda_runtime.h>
#include <cuda_fp16.h>
#include <cstdint>
#include <cstddef>

#define T_STEPS 512
#define DH      2048
#define DI      64
#define DO      64
#define BATCH   128
#define USTR    72               // padded u32/float stride (72 mod 32 = 8)

// ---- device scratch ----
__device__ float    g_base[DH * BATCH];
__device__ float    g_part[4 * DH * BATCH];
__device__ unsigned g_win_h[128 * 4 * 32 * 4];   // [ht128][kt4][lane] uint4
__device__ unsigned g_wout_h[16 * 8 * 4 * 32 * 4]; // [c16][kt8][mt4][lane] uint4 (natural K)
__device__ unsigned g_wfrag[4 * 32 * 32 * 4 * 32 * 4];
__device__ unsigned g_spk[1024 * 128];

__device__ __forceinline__ float sigm_exact(float x) {
    return __fdividef(1.0f, 1.0f + __expf(-x));
}
__device__ __forceinline__ float sigm(float x) {
    float t;
    asm("tanh.approx.f32 %0, %1;" : "=f"(t) : "f"(0.5f * x));
    return fmaf(0.5f, t, 0.5f);
}
__device__ __forceinline__ unsigned packh2(float a, float b) {
    __half2 h = __floats2half2_rn(a, b);   // a -> low half
    return *(unsigned*)&h;
}
__device__ __forceinline__ void mma_f16(float* c, uint4 a, unsigned b0, unsigned b1) {
    asm volatile("mma.sync.aligned.m16n8k16.row.col.f32.f16.f16.f32 "
                 "{%0,%1,%2,%3}, {%4,%5,%6,%7}, {%8,%9}, {%0,%1,%2,%3};"
                 : "+f"(c[0]), "+f"(c[1]), "+f"(c[2]), "+f"(c[3])
                 : "r"(a.x), "r"(a.y), "r"(a.z), "r"(a.w), "r"(b0), "r"(b1));
}

// ---------- kernel 1: packing ----------
__global__ void pack_all_kernel(const float* __restrict__ win,
                                const float* __restrict__ wout,
                                const float* __restrict__ r0,
                                const float* __restrict__ w_) {
    int bx = blockIdx.x;
    int tid = threadIdx.x;
    if (bx < 128) {
        int tg = (bx & 63) * 256 + tid;       // 0..16383
        int lane = tg & 31;
        uint4 oh;
        if (bx < 64) {
            // win: [ht][kt][lane], ht = h/16
            int kt = (tg >> 5) & 3;
            int ht = tg >> 7;                  // 0..127
            int r  = ht * 16 + (lane >> 2);
            int k0 = kt * 16 + 2 * (lane & 3);
            oh.x = packh2(win[r * DI + k0],           win[r * DI + k0 + 1]);
            oh.y = packh2(win[(r + 8) * DI + k0],     win[(r + 8) * DI + k0 + 1]);
            oh.z = packh2(win[r * DI + k0 + 8],       win[r * DI + k0 + 9]);
            oh.w = packh2(win[(r + 8) * DI + k0 + 8], win[(r + 8) * DI + k0 + 9]);
            *(uint4*)(g_win_h + (size_t)tg * 4) = oh;
        } else {
            // wout natural K: [c16][kt8][mt4][lane]
            int mt = (tg >> 5) & 3;
            int kt = (tg >> 7) & 7;
            int c  = tg >> 10;                 // 0..15
            int r  = mt * 16 + (lane >> 2);
            int k0 = c * 128 + kt * 16 + 2 * (lane & 3);
            oh.x = packh2(wout[r * DH + k0],           wout[r * DH + k0 + 1]);
            oh.y = packh2(wout[(r + 8) * DH + k0],     wout[(r + 8) * DH + k0 + 1]);
            oh.z = packh2(wout[r * DH + k0 + 8],       wout[r * DH + k0 + 9]);
            oh.w = packh2(wout[(r + 8) * DH + k0 + 8], wout[(r + 8) * DH + k0 + 9]);
            *(uint4*)(g_wout_h + (size_t)tg * 4) = oh;
        }
    } else if (bx < 384) {
        int i = (bx - 128) * 256 + tid;
        int bp = i & 63;
        int kp = i >> 6;
        float2 ra = *(const float2*)(r0 + (size_t)(2 * kp) * BATCH + 2 * bp);
        float2 rb = *(const float2*)(r0 + (size_t)(2 * kp + 1) * BATCH + 2 * bp);
        uint2 o;
        o.x = packh2(sigm_exact(ra.x), sigm_exact(rb.x));
        o.y = packh2(sigm_exact(ra.y), sigm_exact(rb.y));
        *(uint2*)(g_spk + (size_t)kp * BATCH + 2 * bp) = o;
    } else {
        int tg = (bx - 384) * 256 + tid;
        int lane = tg & 31;
        int mt = (tg >> 5) & 3;
        int kt = (tg >> 7) & 31;
        int hc = (tg >> 12) & 31;
        int kq = tg >> 17;
        int r  = hc * 64 + mt * 16 + (lane >> 2);
        int k0 = kq * 512 + kt * 16 + 2 * (lane & 3);
        uint4 oh;
        oh.x = packh2(fabsf(w_[(size_t)r * DH + k0]),       fabsf(w_[(size_t)r * DH + k0 + 1]));
        oh.y = packh2(fabsf(w_[(size_t)(r + 8) * DH + k0]), fabsf(w_[(size_t)(r + 8) * DH + k0 + 1]));
        oh.z = packh2(fabsf(w_[(size_t)r * DH + k0 + 8]),   fabsf(w_[(size_t)r * DH + k0 + 9]));
        oh.w = packh2(fabsf(w_[(size_t)(r + 8) * DH + k0 + 8]), fabsf(w_[(size_t)(r + 8) * DH + k0 + 9]));
        *(uint4*)(g_wfrag + (size_t)tg * 4) = oh;
    }
}

// ---------- kernel 2: base GEMM partials ----------
__global__ void __launch_bounds__(256)
base_gemm_kernel() {
    int bx = blockIdx.x;
    int kq = bx >> 6;
    int hc = (bx >> 1) & 31;
    int nh = bx & 1;
    int tid  = threadIdx.x;
    int lane = tid & 31;
    int w    = tid >> 5;
    int qq   = lane & 3;
    int rr   = lane >> 2;
    int n    = nh * 64 + w * 8 + rr;

    float C[4][4];
#pragma unroll
    for (int a = 0; a < 4; ++a)
#pragma unroll
        for (int q = 0; q < 4; ++q) C[a][q] = 0.0f;

    const uint4* Af = ((const uint4*)g_wfrag) + ((size_t)(kq * 32 + hc) * 32) * 128;
#pragma unroll 4
    for (int kt = 0; kt < 32; ++kt) {
        int kp = kq * 256 + kt * 8;
        unsigned b0 = g_spk[(size_t)(kp + qq) * BATCH + n];
        unsigned b1 = g_spk[(size_t)(kp + 4 + qq) * BATCH + n];
#pragma unroll
        for (int mt = 0; mt < 4; ++mt)
            mma_f16(C[mt], Af[(kt * 4 + mt) * 32 + lane], b0, b1);
    }
    float* dst = g_part + (size_t)kq * DH * BATCH;
    int n0 = nh * 64 + w * 8 + 2 * qq;
#pragma unroll
    for (int mt = 0; mt < 4; ++mt)
#pragma unroll
        for (int hh = 0; hh < 2; ++hh) {
            int h = hc * 64 + mt * 16 + hh * 8 + rr;
            *(float2*)(dst + (size_t)h * BATCH + n0) =
                make_float2(C[mt][hh * 2], C[mt][hh * 2 + 1]);
        }
}

// ---------- kernel 3: base reduce ----------
__global__ void base_reduce_kernel(const float* __restrict__ r0,
                                   const float* __restrict__ taus) {
    int i4 = (blockIdx.x * blockDim.x + threadIdx.x) * 4;
    int h  = i4 >> 7;
    float alpha = 1.0f / taus[h];
    float om = 1.0f - alpha;
    float4 rv = *(const float4*)(r0 + i4);
    float4 p0 = *(const float4*)(g_part + i4);
    float4 p1 = *(const float4*)(g_part + DH * BATCH + i4);
    float4 p2 = *(const float4*)(g_part + 2 * DH * BATCH + i4);
    float4 p3 = *(const float4*)(g_part + 3 * DH * BATCH + i4);
    float4 o;
    o.x = om * rv.x + alpha * (p0.x + p1.x + p2.x + p3.x);
    o.y = om * rv.y + alpha * (p0.y + p1.y + p2.y + p3.y);
    o.z = om * rv.z + alpha * (p0.z + p1.z + p2.z + p3.z);
    o.w = om * rv.w + alpha * (p0.w + p1.w + p2.w + p3.w);
    *(float4*)(g_base + i4) = o;
}

// ---------- kernel 4: main (fused, coalesced epilogue) ----------
// smem (u32): u 0..2304 | T 2304..11520 (floats) | S 11520..16128
#define oT   2304
#define oS   11520
#define SMEM_U32 16128

__global__ void __launch_bounds__(256, 2)
main_kernel(const float* __restrict__ u,
            const float* __restrict__ noise,
            const float* __restrict__ bias,
            float* __restrict__ out) {
    extern __shared__ unsigned smu[];
    unsigned* uh = smu;
    float*    T  = (float*)(smu + oT);
    unsigned* S  = smu + oS;

    int tid  = threadIdx.x;
    int lane = tid & 31;
    int w    = tid >> 5;
    int qq   = lane & 3;
    int rr   = lane >> 2;

    int t  = blockIdx.x >> 1;
    int nb = (blockIdx.x & 1) * 64;

    float* xsout = out + (size_t)T_STEPS * DO * BATCH;

    // ---- stage u[t] slice (fp16 hi, k-pair layout) ----
    {
        const float* ut = u + (size_t)t * DI * BATCH + nb;
#pragma unroll
        for (int i = 0; i < 4; ++i) {
            int idx = tid + i * 256;
            int dp  = idx >> 5;
            int b2  = (idx & 31) * 2;
            float2 ra = *(const float2*)(ut + (2 * dp) * BATCH + b2);
            float2 rb = *(const float2*)(ut + (2 * dp + 1) * BATCH + b2);
            *(uint2*)(uh + dp * USTR + b2) =
                make_uint2(packh2(ra.x, rb.x), packh2(ra.y, rb.y));
        }
    }

    float* Tw = T + w * (16 * USTR);
    int gb = nb + 2 * lane;

    float C2[4][4];
#pragma unroll
    for (int a = 0; a < 4; ++a)
#pragma unroll
        for (int q = 0; q < 4; ++q) C2[a][q] = 0.0f;

    // A1 frags for chunk 0 (ht = w)
    uint4 A1c[4];
#pragma unroll
    for (int kt = 0; kt < 4; ++kt)
        A1c[kt] = ((const uint4*)g_win_h)[(w * 4 + kt) * 32 + lane];

    // noise/base prefetch ring: pairs 0,1 of chunk 0
    float2 pnz[2][2], pbs[2][2];
#pragma unroll
    for (int s = 0; s < 2; ++s) {
        int h0 = w * 16 + 2 * s;
        pnz[s][0] = *(const float2*)(noise + ((size_t)t * DH + h0) * BATCH + gb);
        pnz[s][1] = *(const float2*)(noise + ((size_t)t * DH + h0 + 1) * BATCH + gb);
        pbs[s][0] = *(const float2*)(g_base + (size_t)h0 * BATCH + gb);
        pbs[s][1] = *(const float2*)(g_base + (size_t)(h0 + 1) * BATCH + gb);
    }

    __syncthreads();   // u staged

    for (int c = 0; c < 16; ++c) {
        // prefetch A1 for next chunk
        uint4 A1n[4];
        if (c < 15) {
#pragma unroll
            for (int kt = 0; kt < 4; ++kt)
                A1n[kt] = ((const uint4*)g_win_h)[(((c + 1) * 8 + w) * 4 + kt) * 32 + lane];
        }

        // ---- GEMM1: C1 = win(16 rows) @ u (16x64x64) ----
        float C1[8][4];
#pragma unroll
        for (int a = 0; a < 8; ++a)
#pragma unroll
            for (int q = 0; q < 4; ++q) C1[a][q] = 0.0f;
#pragma unroll
        for (int kt = 0; kt < 4; ++kt) {
#pragma unroll
            for (int nt = 0; nt < 8; ++nt) {
                unsigned b0 = uh[(kt * 8 + qq) * USTR + nt * 8 + rr];
                unsigned b1 = uh[(kt * 8 + 4 + qq) * USTR + nt * 8 + rr];
                mma_f16(C1[nt], A1c[kt], b0, b1);
            }
        }

        // ---- warp-private fragment transpose into Tw ----
#pragma unroll
        for (int nt = 0; nt < 8; ++nt) {
            int col = nt * 8 + 2 * qq;
            *(float2*)(Tw + rr * USTR + col)       = make_float2(C1[nt][0], C1[nt][1]);
            *(float2*)(Tw + (rr + 8) * USTR + col) = make_float2(C1[nt][2], C1[nt][3]);
        }
        __syncthreads();   // sync_a: T visible; GEMM2(c-1) done -> S writable

        // ---- epilogue: 8 row-pairs, all-coalesced ----
        int R0c = c * 128 + w * 16;
#pragma unroll
        for (int p = 0; p < 8; ++p) {
            int sl = p & 1;
            float2 xr0 = *(const float2*)(Tw + (2 * p) * USTR + 2 * lane);
            float2 xr1 = *(const float2*)(Tw + (2 * p + 1) * USTR + 2 * lane);
            float x00 = xr0.x + pnz[sl][0].x + pbs[sl][0].x;
            float x01 = xr0.y + pnz[sl][0].y + pbs[sl][0].y;
            float x10 = xr1.x + pnz[sl][1].x + pbs[sl][1].x;
            float x11 = xr1.y + pnz[sl][1].y + pbs[sl][1].y;
            size_t gx = ((size_t)t * DH + R0c + 2 * p) * BATCH + gb;
            *(float2*)(xsout + gx)         = make_float2(x00, x01);
            *(float2*)(xsout + gx + BATCH) = make_float2(x10, x11);
            *(uint2*)(S + (w * 8 + p) * USTR + 2 * lane) =
                make_uint2(packh2(sigm(x00), sigm(x10)),
                           packh2(sigm(x01), sigm(x11)));
            // prefetch pair p+2 (may roll into next chunk)
            int pg = p + 2;
            if (pg < 8 || c < 15) {
                int hld = (pg < 8) ? (R0c + 2 * pg) : (R0c + 128 + 2 * (pg - 8));
                pnz[sl][0] = *(const float2*)(noise + ((size_t)t * DH + hld) * BATCH + gb);
                pnz[sl][1] = *(const float2*)(noise + ((size_t)t * DH + hld + 1) * BATCH + gb);
                pbs[sl][0] = *(const float2*)(g_base + (size_t)hld * BATCH + gb);
                pbs[sl][1] = *(const float2*)(g_base + (size_t)(hld + 1) * BATCH + gb);
            }
        }
        __syncthreads();   // sync_b: S complete

        // ---- GEMM2: C2 += wout(64 x this 128-h chunk) @ S ----
#pragma unroll
        for (int kt = 0; kt < 8; ++kt) {
            unsigned b0 = S[(kt * 8 + qq) * USTR + w * 8 + rr];
            unsigned b1 = S[(kt * 8 + 4 + qq) * USTR + w * 8 + rr];
#pragma unroll
            for (int mt = 0; mt < 4; ++mt) {
                uint4 a4 = ((const uint4*)g_wout_h)[((c * 8 + kt) * 4 + mt) * 32 + lane];
                mma_f16(C2[mt], a4, b0, b1);
            }
        }

#pragma unroll
        for (int kt = 0; kt < 4; ++kt) A1c[kt] = A1n[kt];
    }

    // ---- outputs[t] ----
    int n0 = nb + w * 8 + 2 * qq;
#pragma unroll
    for (int mt = 0; mt < 4; ++mt) {
        int o0 = mt * 16 + rr;
        float bv0 = __ldg(bias + o0);
        float bv8 = __ldg(bias + o0 + 8);
        *(float2*)(out + ((size_t)t * DO + o0) * BATCH + n0) =
            make_float2(C2[mt][0] + bv0, C2[mt][1] + bv0);
        *(float2*)(out + ((size_t)t * DO + o0 + 8) * BATCH + n0) =
            make_float2(C2[mt][2] + bv8, C2[mt][3] + bv8);
    }
}

extern "C" void kernel_launch(void* const* d_in, const int* in_sizes, int n_in,
                              void* d_out, int out_size) {
    const float* u     = (const float*)d_in[0];
    const float* r0    = (const float*)d_in[1];
    const float* noise = (const float*)d_in[2];
    const float* win   = (const float*)d_in[3];
    const float* w_    = (const float*)d_in[4];
    // d_in[5] = m_diag: unused — |_w * (+-1)| == |_w|
    const float* wout  = (const float*)d_in[6];
    const float* bias  = (const float*)d_in[7];
    const float* taus  = (const float*)d_in[8];
    float* out = (float*)d_out;

    const int main_smem = SMEM_U32 * 4;   // 64512 B -> 2 blocks/SM
    cudaFuncSetAttribute(main_kernel, cudaFuncAttributeMaxDynamicSharedMemorySize, main_smem);

    pack_all_kernel<<<2432, 256>>>(win, wout, r0, w_);
    base_gemm_kernel<<<256, 256>>>();
    base_reduce_kernel<<<256, 256>>>(r0, taus);
    main_kernel<<<2 * T_STEPS, 256, main_smem>>>(u, noise, bias, out);
}